// round 5
// baseline (speedup 1.0000x reference)
#include <cuda_runtime.h>

// JacobiConv: L=3, alpha=beta=1, SCALING=3
// Inputs (metadata order):
//   d_in[0] x           : float32 [100000, 64]
//   d_in[1] edge_index  : int64 OR int32 [2, 1250000] (row = [0], col = [1]) — detected at runtime
//   d_in[2] edge_weight : float32 [1250000]
//   d_in[3] gammas      : float32 [4, 1]
// Output: float32 [100000, 64]

static constexpr int N_NODES = 100000;
static constexpr int N_EDGES = 1250000;
static constexpr int NELEM   = N_NODES * 64;         // 6,400,000 floats
static constexpr int NVEC    = NELEM / 4;            // 1,600,000 float4
static constexpr float SCALING = 3.0f;

// Recurrence constants (alpha = beta = 1):
//   z1 = 2*Az0
//   l=2: c0=64,  c2=120, c3=48   -> z2 = 1.875*Az1 - 0.75*z0
//   l=3: c0=180, c2=336, c3=144  -> z3 = (336/180)*Az2 - 0.8*z1
static constexpr float K1S = 2.0f;
static constexpr float A2  = 120.0f / 64.0f;
static constexpr float B2  = -48.0f / 64.0f;
static constexpr float A3  = 336.0f / 180.0f;
static constexpr float B3  = -144.0f / 180.0f;

// Scratch (__device__ globals: allocation-free rule). 16B+ aligned.
__device__ __align__(256) float g_S [NELEM];   // SpMM accumulator
__device__ __align__(256) float g_D1[NELEM];   // z1
__device__ __align__(256) float g_D2[NELEM];   // z2
__device__ __align__(256) int2  g_edge[N_EDGES];
__device__ unsigned g_i32flag;                 // 0 => edge_index is int64, nonzero => int32

// ---------------------------------------------------------------------------
__global__ void __launch_bounds__(256) zero_S_kernel() {
    int i = blockIdx.x * 256 + threadIdx.x;
    reinterpret_cast<float4*>(g_S)[i] = make_float4(0.f, 0.f, 0.f, 0.f);
    if (i == 0) g_i32flag = 0u;
}

// Detect edge_index dtype: OR all odd 32-bit words of the first 2*N_EDGES words.
// int64 data (values < 2^31): every odd word is the zero high-half -> OR == 0.
// int32 data: odd words are 1.25M random node ids -> OR != 0 (certain).
__global__ void __launch_bounds__(256) detect_kernel(const unsigned* __restrict__ ei32) {
    int i = blockIdx.x * 256 + threadIdx.x;
    unsigned v = (i < N_EDGES) ? ei32[2 * i + 1] : 0u;
    v = __reduce_or_sync(0xFFFFFFFFu, v);
    if ((threadIdx.x & 31) == 0 && v) atomicOr(&g_i32flag, 1u);
}

// Materialize int2 {row, col} per edge under the detected interpretation.
__global__ void __launch_bounds__(256) convert_kernel(const void* __restrict__ ei) {
    int e = blockIdx.x * 256 + threadIdx.x;
    if (e >= N_EDGES) return;
    int r, c;
    if (g_i32flag) {
        const int* p = (const int*)ei;
        r = p[e]; c = p[e + N_EDGES];
    } else {
        const long long* p = (const long long*)ei;
        r = (int)p[e]; c = (int)p[e + N_EDGES];
    }
    g_edge[e] = make_int2(r, c);
}

// ---------------------------------------------------------------------------
// SpMM scatter: g_S[row_e] += w_e * z[col_e].
// 16 threads/edge, one float4 (16B) each: 256B-coalesced gather per edge,
// red.global.add.v4.f32 fire-and-forget scatter. Out-of-range indices are
// predicated out (defense: can never IMA even if detection were wrong).
__global__ void __launch_bounds__(256) spmm_kernel(
    const float* __restrict__ w, const float* __restrict__ z)
{
    unsigned t    = blockIdx.x * 256u + threadIdx.x;
    unsigned e    = t >> 4;
    unsigned lane = t & 15u;
    if (e >= (unsigned)N_EDGES) return;

    int2 rc = g_edge[e];                     // 16 lanes broadcast-load same 8B
    if ((unsigned)rc.x >= (unsigned)N_NODES || (unsigned)rc.y >= (unsigned)N_NODES) return;
    float wt = __ldg(w + e);

    float4 v = __ldg(reinterpret_cast<const float4*>(z) + (unsigned)rc.y * 16u + lane);
    float* dst = g_S + (unsigned)rc.x * 64u + lane * 4u;
    asm volatile("red.global.add.v4.f32 [%0], {%1, %2, %3, %4};"
                 :: "l"(dst),
                    "f"(v.x * wt), "f"(v.y * wt), "f"(v.z * wt), "f"(v.w * wt)
                 : "memory");
}

// ---------------------------------------------------------------------------
__device__ __forceinline__ void load_coefs(const float* __restrict__ gam, float c[4]) {
    c[0] = tanhf(gam[0]) * SCALING;
    c[1] = c[0] * tanhf(gam[1]) * SCALING;
    c[2] = c[1] * tanhf(gam[2]) * SCALING;
    c[3] = c[2] * tanhf(gam[3]) * SCALING;
}

// combine1: z1 = 2*S; D1 = z1; out = 0.25*(c0*x + c1*z1); S = 0
__global__ void __launch_bounds__(256) combine1_kernel(
    const float* __restrict__ x, const float* __restrict__ gam,
    float* __restrict__ out)
{
    int i = blockIdx.x * 256 + threadIdx.x;
    float c[4]; load_coefs(gam, c);

    float4 xv = reinterpret_cast<const float4*>(x)[i];
    float4 sv = reinterpret_cast<float4*>(g_S)[i];

    float4 z1 = make_float4(K1S * sv.x, K1S * sv.y, K1S * sv.z, K1S * sv.w);
    reinterpret_cast<float4*>(g_D1)[i] = z1;

    float4 o;
    o.x = 0.25f * (c[0] * xv.x + c[1] * z1.x);
    o.y = 0.25f * (c[0] * xv.y + c[1] * z1.y);
    o.z = 0.25f * (c[0] * xv.z + c[1] * z1.z);
    o.w = 0.25f * (c[0] * xv.w + c[1] * z1.w);
    reinterpret_cast<float4*>(out)[i] = o;

    reinterpret_cast<float4*>(g_S)[i] = make_float4(0.f, 0.f, 0.f, 0.f);
}

// combine2: z2 = A2*S + B2*x; D2 = z2; out += 0.25*c2*z2; S = 0
__global__ void __launch_bounds__(256) combine2_kernel(
    const float* __restrict__ x, const float* __restrict__ gam,
    float* __restrict__ out)
{
    int i = blockIdx.x * 256 + threadIdx.x;
    float c[4]; load_coefs(gam, c);

    float4 xv = reinterpret_cast<const float4*>(x)[i];
    float4 sv = reinterpret_cast<float4*>(g_S)[i];

    float4 z2;
    z2.x = A2 * sv.x + B2 * xv.x;
    z2.y = A2 * sv.y + B2 * xv.y;
    z2.z = A2 * sv.z + B2 * xv.z;
    z2.w = A2 * sv.w + B2 * xv.w;
    reinterpret_cast<float4*>(g_D2)[i] = z2;

    float4 o = reinterpret_cast<float4*>(out)[i];
    float s = 0.25f * c[2];
    o.x += s * z2.x; o.y += s * z2.y; o.z += s * z2.z; o.w += s * z2.w;
    reinterpret_cast<float4*>(out)[i] = o;

    reinterpret_cast<float4*>(g_S)[i] = make_float4(0.f, 0.f, 0.f, 0.f);
}

// combine3: z3 = A3*S + B3*D1; out += 0.25*c3*z3
__global__ void __launch_bounds__(256) combine3_kernel(
    const float* __restrict__ gam, float* __restrict__ out)
{
    int i = blockIdx.x * 256 + threadIdx.x;
    float c[4]; load_coefs(gam, c);

    float4 sv = reinterpret_cast<float4*>(g_S)[i];
    float4 d1 = reinterpret_cast<float4*>(g_D1)[i];

    float4 z3;
    z3.x = A3 * sv.x + B3 * d1.x;
    z3.y = A3 * sv.y + B3 * d1.y;
    z3.z = A3 * sv.z + B3 * d1.z;
    z3.w = A3 * sv.w + B3 * d1.w;

    float4 o = reinterpret_cast<float4*>(out)[i];
    float s = 0.25f * c[3];
    o.x += s * z3.x; o.y += s * z3.y; o.z += s * z3.z; o.w += s * z3.w;
    reinterpret_cast<float4*>(out)[i] = o;
}

// ---------------------------------------------------------------------------
extern "C" void kernel_launch(void* const* d_in, const int* in_sizes, int n_in,
                              void* d_out, int out_size)
{
    const float* x   = (const float*)d_in[0];
    const void*  ei  = d_in[1];
    const float* w   = (const float*)d_in[2];
    const float* gam = (const float*)d_in[3];
    float*       out = (float*)d_out;

    float* dD1;
    float* dD2;
    cudaGetSymbolAddress((void**)&dD1, g_D1);
    cudaGetSymbolAddress((void**)&dD2, g_D2);

    const int VB = NVEC / 256;                 // 6250 blocks (exact)
    const int EB = (N_EDGES * 16) / 256;       // 78125 blocks (exact)
    const int CB = (N_EDGES + 255) / 256;      // 4883 blocks

    zero_S_kernel<<<VB, 256>>>();                               // also clears flag
    detect_kernel<<<CB, 256>>>((const unsigned*)ei);
    convert_kernel<<<CB, 256>>>(ei);

    // l = 1
    spmm_kernel<<<EB, 256>>>(w, x);
    combine1_kernel<<<VB, 256>>>(x, gam, out);

    // l = 2
    spmm_kernel<<<EB, 256>>>(w, dD1);
    combine2_kernel<<<VB, 256>>>(x, gam, out);

    // l = 3
    spmm_kernel<<<EB, 256>>>(w, dD2);
    combine3_kernel<<<VB, 256>>>(gam, out);
}

// round 6
// speedup vs baseline: 1.9137x; 1.9137x over previous
#include <cuda_runtime.h>

// JacobiConv: L=3, alpha=beta=1, SCALING=3 — CSR-gather formulation (no atomics in SpMM)
// Inputs (metadata order):
//   d_in[0] x           : float32 [100000, 64]
//   d_in[1] edge_index  : int64 OR int32 [2, 1250000] (row=[0], col=[1]) — dtype detected at runtime
//   d_in[2] edge_weight : float32 [1250000]
//   d_in[3] gammas      : float32 [4, 1]
// Output: float32 [100000, 64]

static constexpr int N_NODES = 100000;
static constexpr int N_EDGES = 1250000;
static constexpr int NELEM   = N_NODES * 64;
static constexpr float SCALING = 3.0f;

// Recurrence constants (alpha = beta = 1):
static constexpr float K1S = 2.0f;              // z1 = 2*Az0
static constexpr float A2  = 120.0f / 64.0f;    // z2 =  1.875*Az1 - 0.75*z0
static constexpr float B2  = -48.0f / 64.0f;
static constexpr float A3  = 336.0f / 180.0f;   // z3 =  1.8667*Az2 - 0.8*z1
static constexpr float B3  = -144.0f / 180.0f;

static constexpr int SCAN_BLK  = 512;
static constexpr int SCAN_NBLK = (N_NODES + SCAN_BLK - 1) / SCAN_BLK;  // 196

// Scratch (__device__ globals: allocation-free rule).
__device__ __align__(256) float g_D1[NELEM];           // z1
__device__ __align__(256) float g_D2[NELEM];           // z2
__device__ __align__(16)  int2  g_edge[N_EDGES];       // {row, col} (pre-sort)
__device__ __align__(16)  int2  g_cw[N_EDGES];         // {col, float_bits(w)} row-sorted
__device__ int g_count[N_NODES];
__device__ int g_rowptr[N_NODES + 1];
__device__ int g_cursor[N_NODES];
__device__ int g_blocksum[SCAN_NBLK];
__device__ int g_blockoff[SCAN_NBLK];
__device__ unsigned g_i32flag;                         // 0 => int64 indices, 1 => int32

// ---------------------------------------------------------------------------
__global__ void __launch_bounds__(256) init_kernel() {
    int i = blockIdx.x * 256 + threadIdx.x;
    if (i < N_NODES) g_count[i] = 0;
    if (i == 0) g_i32flag = 0u;
}

// Detect dtype: OR the odd 32-bit words of edge_index's first half. int64
// values < 2^31 have zero high words (OR==0); int32 data has random node ids
// there (OR!=0 with certainty over 1.25M samples).
__global__ void __launch_bounds__(256) detect_kernel(const unsigned* __restrict__ ei32) {
    int i = blockIdx.x * 256 + threadIdx.x;
    unsigned v = (i < N_EDGES) ? ei32[2 * i + 1] : 0u;
    v = __reduce_or_sync(0xFFFFFFFFu, v);
    if ((threadIdx.x & 31) == 0 && v) atomicOr(&g_i32flag, 1u);
}

// Materialize {row,col} per edge (clamped: can never IMA) + row histogram.
__global__ void __launch_bounds__(256) convert_hist_kernel(const void* __restrict__ ei) {
    int e = blockIdx.x * 256 + threadIdx.x;
    if (e >= N_EDGES) return;
    int r, c;
    if (g_i32flag) {
        const int* p = (const int*)ei;
        r = p[e]; c = p[e + N_EDGES];
    } else {
        const long long* p = (const long long*)ei;
        r = (int)p[e]; c = (int)p[e + N_EDGES];
    }
    r = min(max(r, 0), N_NODES - 1);
    c = min(max(c, 0), N_NODES - 1);
    g_edge[e] = make_int2(r, c);
    atomicAdd(&g_count[r], 1);
}

// Scan stage A: per-block sums of counts.
__global__ void __launch_bounds__(SCAN_BLK) scanA_kernel() {
    __shared__ int s[SCAN_BLK];
    int t = threadIdx.x;
    int i = blockIdx.x * SCAN_BLK + t;
    s[t] = (i < N_NODES) ? g_count[i] : 0;
    __syncthreads();
    for (int off = SCAN_BLK / 2; off > 0; off >>= 1) {
        if (t < off) s[t] += s[t + off];
        __syncthreads();
    }
    if (t == 0) g_blocksum[blockIdx.x] = s[0];
}

// Scan stage B: exclusive scan of the 196 block sums (single block).
__global__ void __launch_bounds__(256) scanB_kernel() {
    __shared__ int s[256];
    int t = threadIdx.x;
    int v = (t < SCAN_NBLK) ? g_blocksum[t] : 0;
    s[t] = v;
    __syncthreads();
    for (int off = 1; off < 256; off <<= 1) {
        int a = (t >= off) ? s[t - off] : 0;
        __syncthreads();
        s[t] += a;
        __syncthreads();
    }
    if (t < SCAN_NBLK) g_blockoff[t] = s[t] - v;   // exclusive
    if (t == 0) g_rowptr[N_NODES] = N_EDGES;
}

// Scan stage C: block-local exclusive scan + block offset -> rowptr, cursor.
__global__ void __launch_bounds__(SCAN_BLK) scanC_kernel() {
    __shared__ int s[SCAN_BLK];
    int t = threadIdx.x;
    int i = blockIdx.x * SCAN_BLK + t;
    int v = (i < N_NODES) ? g_count[i] : 0;
    s[t] = v;
    __syncthreads();
    for (int off = 1; off < SCAN_BLK; off <<= 1) {
        int a = (t >= off) ? s[t - off] : 0;
        __syncthreads();
        s[t] += a;
        __syncthreads();
    }
    if (i < N_NODES) {
        int excl = g_blockoff[blockIdx.x] + s[t] - v;
        g_rowptr[i] = excl;
        g_cursor[i] = excl;
    }
}

// Scatter edges into row-sorted {col, w} pairs.
__global__ void __launch_bounds__(256) scatter_kernel(const float* __restrict__ w) {
    int e = blockIdx.x * 256 + threadIdx.x;
    if (e >= N_EDGES) return;
    int2 rc = g_edge[e];
    int pos = atomicAdd(&g_cursor[rc.x], 1);
    g_cw[pos] = make_int2(rc.y, __float_as_int(__ldg(w + e)));
}

// ---------------------------------------------------------------------------
__device__ __forceinline__ void load_coefs(const float* __restrict__ gam, float c[4]) {
    c[0] = tanhf(gam[0]) * SCALING;
    c[1] = c[0] * tanhf(gam[1]) * SCALING;
    c[2] = c[1] * tanhf(gam[2]) * SCALING;
    c[3] = c[2] * tanhf(gam[3]) * SCALING;
}

// Fused SpMM (gather, atomic-free) + Jacobi recurrence + output accumulation.
// 16 threads per destination row; each thread owns one float4 (16B) of the
// 256B feature row. Per edge: one 8B broadcast load ({col,w}) + one 16B gather.
template <int LVL>
__global__ void __launch_bounds__(256) spmm_fused_kernel(
    const float* __restrict__ z,     // z_{l-1}
    const float* __restrict__ x,
    const float* __restrict__ gam,
    float* __restrict__ out)
{
    unsigned t    = blockIdx.x * 256u + threadIdx.x;
    unsigned row  = t >> 4;
    unsigned lane = t & 15u;

    int s = g_rowptr[row];
    int e = g_rowptr[row + 1];
    const float4* zv = reinterpret_cast<const float4*>(z);

    float4 acc = make_float4(0.f, 0.f, 0.f, 0.f);
    #pragma unroll 2
    for (int k = s; k < e; ++k) {
        int2  cw = __ldg(&g_cw[k]);
        float wt = __int_as_float(cw.y);
        float4 v = __ldg(zv + (unsigned)cw.x * 16u + lane);
        acc.x += wt * v.x; acc.y += wt * v.y;
        acc.z += wt * v.z; acc.w += wt * v.w;
    }

    float c[4]; load_coefs(gam, c);
    unsigned i = row * 16u + lane;

    if (LVL == 1) {
        float4 z1 = make_float4(K1S * acc.x, K1S * acc.y, K1S * acc.z, K1S * acc.w);
        reinterpret_cast<float4*>(g_D1)[i] = z1;
        float4 xv = __ldg(reinterpret_cast<const float4*>(x) + i);
        float4 o;
        o.x = 0.25f * (c[0] * xv.x + c[1] * z1.x);
        o.y = 0.25f * (c[0] * xv.y + c[1] * z1.y);
        o.z = 0.25f * (c[0] * xv.z + c[1] * z1.z);
        o.w = 0.25f * (c[0] * xv.w + c[1] * z1.w);
        reinterpret_cast<float4*>(out)[i] = o;
    } else if (LVL == 2) {
        float4 xv = __ldg(reinterpret_cast<const float4*>(x) + i);
        float4 z2;
        z2.x = A2 * acc.x + B2 * xv.x;
        z2.y = A2 * acc.y + B2 * xv.y;
        z2.z = A2 * acc.z + B2 * xv.z;
        z2.w = A2 * acc.w + B2 * xv.w;
        reinterpret_cast<float4*>(g_D2)[i] = z2;
        float4 o = reinterpret_cast<float4*>(out)[i];
        float sc = 0.25f * c[2];
        o.x += sc * z2.x; o.y += sc * z2.y; o.z += sc * z2.z; o.w += sc * z2.w;
        reinterpret_cast<float4*>(out)[i] = o;
    } else {
        float4 d1 = reinterpret_cast<float4*>(g_D1)[i];
        float4 z3;
        z3.x = A3 * acc.x + B3 * d1.x;
        z3.y = A3 * acc.y + B3 * d1.y;
        z3.z = A3 * acc.z + B3 * d1.z;
        z3.w = A3 * acc.w + B3 * d1.w;
        float4 o = reinterpret_cast<float4*>(out)[i];
        float sc = 0.25f * c[3];
        o.x += sc * z3.x; o.y += sc * z3.y; o.z += sc * z3.z; o.w += sc * z3.w;
        reinterpret_cast<float4*>(out)[i] = o;
    }
}

// ---------------------------------------------------------------------------
extern "C" void kernel_launch(void* const* d_in, const int* in_sizes, int n_in,
                              void* d_out, int out_size)
{
    const float* x   = (const float*)d_in[0];
    const void*  ei  = d_in[1];
    const float* w   = (const float*)d_in[2];
    const float* gam = (const float*)d_in[3];
    float*       out = (float*)d_out;

    float* dD1;
    float* dD2;
    cudaGetSymbolAddress((void**)&dD1, g_D1);
    cudaGetSymbolAddress((void**)&dD2, g_D2);

    const int NB = (N_NODES + 255) / 256;       // 391
    const int EBc = (N_EDGES + 255) / 256;      // 4883
    const int RB = (N_NODES * 16) / 256;        // 6250 (exact)

    // CSR build (per-call: deterministic work, no caching)
    init_kernel<<<NB, 256>>>();
    detect_kernel<<<EBc, 256>>>((const unsigned*)ei);
    convert_hist_kernel<<<EBc, 256>>>(ei);
    scanA_kernel<<<SCAN_NBLK, SCAN_BLK>>>();
    scanB_kernel<<<1, 256>>>();
    scanC_kernel<<<SCAN_NBLK, SCAN_BLK>>>();
    scatter_kernel<<<EBc, 256>>>(w);

    // Fused SpMM + recurrence + output accumulation
    spmm_fused_kernel<1><<<RB, 256>>>(x,   x, gam, out);
    spmm_fused_kernel<2><<<RB, 256>>>(dD1, x, gam, out);
    spmm_fused_kernel<3><<<RB, 256>>>(dD2, x, gam, out);
}

// round 7
// speedup vs baseline: 2.2095x; 1.1546x over previous
#include <cuda_runtime.h>

// JacobiConv: L=3, alpha=beta=1, SCALING=3 — CSR-gather, single-pass build
// Inputs (metadata order):
//   d_in[0] x           : float32 [100000, 64]
//   d_in[1] edge_index  : int64 OR int32 [2, 1250000] (row=[0], col=[1]) — dtype detected at runtime
//   d_in[2] edge_weight : float32 [1250000]
//   d_in[3] gammas      : float32 [4, 1]
// Output: float32 [100000, 64]

static constexpr int N_NODES = 100000;
static constexpr int N_EDGES = 1250000;
static constexpr int NELEM   = N_NODES * 64;
static constexpr float SCALING = 3.0f;

// Recurrence constants (alpha = beta = 1):
static constexpr float K1S = 2.0f;              // z1 = 2*Az0
static constexpr float A2  = 120.0f / 64.0f;    // z2 = 1.875*Az1 - 0.75*z0
static constexpr float B2  = -48.0f / 64.0f;
static constexpr float A3  = 336.0f / 180.0f;   // z3 = 1.8667*Az2 - 0.8*z1
static constexpr float B3  = -144.0f / 180.0f;

static constexpr int SCAN_BLK  = 512;
static constexpr int SCAN_NBLK = (N_NODES + SCAN_BLK - 1) / SCAN_BLK;  // 196

// Scratch (__device__ globals: allocation-free rule).
__device__ __align__(256) float g_D1[NELEM];       // z1
__device__ __align__(256) float g_D2[NELEM];       // z2
__device__ __align__(16)  int4  g_e4[N_EDGES];     // {row, col, pos_in_row, w_bits}
__device__ __align__(16)  int2  g_cw[N_EDGES];     // {col, w_bits} row-grouped
__device__ int g_count[N_NODES];
__device__ int g_start[N_NODES];                   // arbitrary-order segment bases
__device__ int g_ctr;
__device__ unsigned g_i32flag;                     // 0 => int64 indices, 1 => int32

// ---------------------------------------------------------------------------
// Zero counters + detect edge_index dtype (block 0 samples 512 odd 32-bit
// words: int64 data has zero high-halves; int32 data has random node ids
// there -> OR != 0 with certainty).
__global__ void __launch_bounds__(256) init_detect_kernel(const unsigned* __restrict__ ei32) {
    int i = blockIdx.x * 256 + threadIdx.x;
    if (i < N_NODES) g_count[i] = 0;
    if (blockIdx.x == 0) {
        if (threadIdx.x == 0) { g_ctr = 0; g_i32flag = 0u; }
        __syncthreads();
        unsigned v = ei32[2 * threadIdx.x + 1];
        v = __reduce_or_sync(0xFFFFFFFFu, v);
        if ((threadIdx.x & 31) == 0 && v) atomicOr(&g_i32flag, 1u);
    }
}

// Decode (clamped: can never IMA), histogram rows; the histogram atomic's
// return value IS the edge's position within its row (stored for scatter).
__global__ void __launch_bounds__(256) convert_hist_kernel(
    const void* __restrict__ ei, const float* __restrict__ w)
{
    int e = blockIdx.x * 256 + threadIdx.x;
    if (e >= N_EDGES) return;
    int r, c;
    if (g_i32flag) {
        const int* p = (const int*)ei;
        r = p[e]; c = p[e + N_EDGES];
    } else {
        const long long* p = (const long long*)ei;
        r = (int)p[e]; c = (int)p[e + N_EDGES];
    }
    r = min(max(r, 0), N_NODES - 1);
    c = min(max(c, 0), N_NODES - 1);
    int pos = atomicAdd(&g_count[r], 1);
    g_e4[e] = make_int4(r, c, pos, __float_as_int(__ldg(w + e)));
}

// One-kernel segment assignment: block-local exclusive scan of counts, then a
// single atomicAdd per block claims a contiguous base. Segment order across
// blocks is arbitrary — the gather SpMM only needs {start, count} per row.
__global__ void __launch_bounds__(SCAN_BLK) assign_kernel() {
    __shared__ int s[SCAN_BLK];
    __shared__ int sbase;
    int t = threadIdx.x;
    int i = blockIdx.x * SCAN_BLK + t;
    int v = (i < N_NODES) ? g_count[i] : 0;
    s[t] = v;
    __syncthreads();
    #pragma unroll
    for (int off = 1; off < SCAN_BLK; off <<= 1) {
        int a = (t >= off) ? s[t - off] : 0;
        __syncthreads();
        s[t] += a;                      // inclusive scan
        __syncthreads();
    }
    if (t == SCAN_BLK - 1) sbase = atomicAdd(&g_ctr, s[SCAN_BLK - 1]);
    __syncthreads();
    if (i < N_NODES) g_start[i] = sbase + s[t] - v;   // exclusive + block base
}

// Atomic-free scatter into row-grouped {col, w}.
__global__ void __launch_bounds__(256) scatter_kernel() {
    int e = blockIdx.x * 256 + threadIdx.x;
    if (e >= N_EDGES) return;
    int4 q = g_e4[e];
    g_cw[g_start[q.x] + q.z] = make_int2(q.y, q.w);
}

// ---------------------------------------------------------------------------
__device__ __forceinline__ void load_coefs(const float* __restrict__ gam, float c[4]) {
    c[0] = tanhf(gam[0]) * SCALING;
    c[1] = c[0] * tanhf(gam[1]) * SCALING;
    c[2] = c[1] * tanhf(gam[2]) * SCALING;
    c[3] = c[2] * tanhf(gam[3]) * SCALING;
}

// Fused SpMM (gather, atomic-free) + Jacobi recurrence + output accumulation.
// 16 threads per destination row; each thread owns one float4 of the 256B
// feature row. Per edge: one 8B broadcast load ({col,w}) + one 16B gather.
template <int LVL>
__global__ void __launch_bounds__(256) spmm_fused_kernel(
    const float* __restrict__ z,     // z_{l-1}
    const float* __restrict__ x,
    const float* __restrict__ gam,
    float* __restrict__ out)
{
    unsigned t    = blockIdx.x * 256u + threadIdx.x;
    unsigned row  = t >> 4;
    unsigned lane = t & 15u;

    int s   = g_start[row];
    int e   = s + g_count[row];
    const float4* zv = reinterpret_cast<const float4*>(z);

    float4 acc = make_float4(0.f, 0.f, 0.f, 0.f);
    #pragma unroll 4
    for (int k = s; k < e; ++k) {
        int2  cw = __ldg(&g_cw[k]);
        float wt = __int_as_float(cw.y);
        float4 v = __ldg(zv + (unsigned)cw.x * 16u + lane);
        acc.x += wt * v.x; acc.y += wt * v.y;
        acc.z += wt * v.z; acc.w += wt * v.w;
    }

    float c[4]; load_coefs(gam, c);
    unsigned i = row * 16u + lane;

    if (LVL == 1) {
        float4 z1 = make_float4(K1S * acc.x, K1S * acc.y, K1S * acc.z, K1S * acc.w);
        reinterpret_cast<float4*>(g_D1)[i] = z1;
        float4 xv = __ldg(reinterpret_cast<const float4*>(x) + i);
        float4 o;
        o.x = 0.25f * (c[0] * xv.x + c[1] * z1.x);
        o.y = 0.25f * (c[0] * xv.y + c[1] * z1.y);
        o.z = 0.25f * (c[0] * xv.z + c[1] * z1.z);
        o.w = 0.25f * (c[0] * xv.w + c[1] * z1.w);
        reinterpret_cast<float4*>(out)[i] = o;
    } else if (LVL == 2) {
        float4 xv = __ldg(reinterpret_cast<const float4*>(x) + i);
        float4 z2;
        z2.x = A2 * acc.x + B2 * xv.x;
        z2.y = A2 * acc.y + B2 * xv.y;
        z2.z = A2 * acc.z + B2 * xv.z;
        z2.w = A2 * acc.w + B2 * xv.w;
        reinterpret_cast<float4*>(g_D2)[i] = z2;
        float4 o = reinterpret_cast<float4*>(out)[i];
        float sc = 0.25f * c[2];
        o.x += sc * z2.x; o.y += sc * z2.y; o.z += sc * z2.z; o.w += sc * z2.w;
        reinterpret_cast<float4*>(out)[i] = o;
    } else {
        float4 d1 = reinterpret_cast<float4*>(g_D1)[i];
        float4 z3;
        z3.x = A3 * acc.x + B3 * d1.x;
        z3.y = A3 * acc.y + B3 * d1.y;
        z3.z = A3 * acc.z + B3 * d1.z;
        z3.w = A3 * acc.w + B3 * d1.w;
        float4 o = reinterpret_cast<float4*>(out)[i];
        float sc = 0.25f * c[3];
        o.x += sc * z3.x; o.y += sc * z3.y; o.z += sc * z3.z; o.w += sc * z3.w;
        reinterpret_cast<float4*>(out)[i] = o;
    }
}

// ---------------------------------------------------------------------------
extern "C" void kernel_launch(void* const* d_in, const int* in_sizes, int n_in,
                              void* d_out, int out_size)
{
    const float* x   = (const float*)d_in[0];
    const void*  ei  = d_in[1];
    const float* w   = (const float*)d_in[2];
    const float* gam = (const float*)d_in[3];
    float*       out = (float*)d_out;

    float* dD1;
    float* dD2;
    cudaGetSymbolAddress((void**)&dD1, g_D1);
    cudaGetSymbolAddress((void**)&dD2, g_D2);

    const int NB  = (N_NODES + 255) / 256;      // 391
    const int EB  = (N_EDGES + 255) / 256;      // 4883
    const int RB  = (N_NODES * 16) / 256;       // 6250 (exact)

    // CSR build: 4 launches
    init_detect_kernel<<<NB, 256>>>((const unsigned*)ei);
    convert_hist_kernel<<<EB, 256>>>(ei, w);
    assign_kernel<<<SCAN_NBLK, SCAN_BLK>>>();
    scatter_kernel<<<EB, 256>>>();

    // Fused SpMM + recurrence + output accumulation: 3 launches
    spmm_fused_kernel<1><<<RB, 256>>>(x,   x, gam, out);
    spmm_fused_kernel<2><<<RB, 256>>>(dD1, x, gam, out);
    spmm_fused_kernel<3><<<RB, 256>>>(dD2, x, gam, out);
}

// round 10
// speedup vs baseline: 2.3563x; 1.0664x over previous
#include <cuda_runtime.h>

// JacobiConv: L=3, alpha=beta=1, SCALING=3 — CSR-gather, MLP-optimized build
// Inputs (metadata order):
//   d_in[0] x           : float32 [100000, 64]
//   d_in[1] edge_index  : int64 OR int32 [2, 1250000] (row=[0], col=[1]) — dtype detected at runtime
//   d_in[2] edge_weight : float32 [1250000]
//   d_in[3] gammas      : float32 [4, 1]
// Output: float32 [100000, 64]

static constexpr int N_NODES = 100000;
static constexpr int N_EDGES = 1250000;            // divisible by 4
static constexpr int NELEM   = N_NODES * 64;
static constexpr float SCALING = 3.0f;

// Recurrence constants (alpha = beta = 1):
static constexpr float K1S = 2.0f;              // z1 = 2*Az0
static constexpr float A2  = 120.0f / 64.0f;    // z2 = 1.875*Az1 - 0.75*z0
static constexpr float B2  = -48.0f / 64.0f;
static constexpr float A3  = 336.0f / 180.0f;   // z3 = 1.8667*Az2 - 0.8*z1
static constexpr float B3  = -144.0f / 180.0f;

static constexpr int SCAN_BLK  = 512;
static constexpr int SCAN_NBLK = (N_NODES + SCAN_BLK - 1) / SCAN_BLK;  // 196

// row in bits [0:17), pos-in-row in bits [17:32)
static constexpr unsigned ROW_MASK = 0x1FFFFu;

// Scratch (__device__ globals: allocation-free rule).
__device__ __align__(256) float g_D1[NELEM];       // z1
__device__ __align__(256) float g_D2[NELEM];       // z2
__device__ __align__(16)  int2  g_p2[N_EDGES];     // {row|pos<<17, col}
__device__ __align__(16)  int2  g_cw[N_EDGES];     // {col, w_bits} row-grouped
__device__ __align__(16)  int2  g_seg[N_NODES];    // {start, count}
__device__ int g_count[N_NODES];
__device__ int g_ctr;
__device__ unsigned g_i32flag;                     // 0 => int64 indices, 1 => int32

// ---------------------------------------------------------------------------
// Zero counters + detect edge_index dtype (block 0 samples 512 odd 32-bit
// words: int64 values <2^31 have zero high-halves; int32 data has random node
// ids there -> OR != 0 with certainty).
__global__ void __launch_bounds__(256) init_detect_kernel(const unsigned* __restrict__ ei32) {
    int i = blockIdx.x * 256 + threadIdx.x;
    if (i < N_NODES) g_count[i] = 0;
    if (blockIdx.x == 0) {
        if (threadIdx.x == 0) { g_ctr = 0; g_i32flag = 0u; }
        __syncthreads();
        unsigned v = ei32[2 * threadIdx.x + 1];
        v = __reduce_or_sync(0xFFFFFFFFu, v);
        if ((threadIdx.x & 31) == 0 && v) atomicOr(&g_i32flag, 1u);
    }
}

// Decode 4 edges/thread (vector loads), histogram rows; the atomic's return
// value IS the edge's position within its row, packed with the row id.
__global__ void __launch_bounds__(256) convert_hist_kernel(const void* __restrict__ ei) {
    int t  = blockIdx.x * 256 + threadIdx.x;
    int e0 = t * 4;
    if (e0 >= N_EDGES) return;

    int r[4], c[4];
    if (g_i32flag) {
        int4 rv = __ldg(reinterpret_cast<const int4*>(ei) + t);
        int4 cv = __ldg(reinterpret_cast<const int4*>((const int*)ei + N_EDGES) + t);
        r[0]=rv.x; r[1]=rv.y; r[2]=rv.z; r[3]=rv.w;
        c[0]=cv.x; c[1]=cv.y; c[2]=cv.z; c[3]=cv.w;
    } else {
        const longlong2* rp = reinterpret_cast<const longlong2*>(ei);
        const longlong2* cp = reinterpret_cast<const longlong2*>((const long long*)ei + N_EDGES);
        longlong2 r01 = __ldg(rp + 2*t), r23 = __ldg(rp + 2*t + 1);
        longlong2 c01 = __ldg(cp + 2*t), c23 = __ldg(cp + 2*t + 1);
        r[0]=(int)r01.x; r[1]=(int)r01.y; r[2]=(int)r23.x; r[3]=(int)r23.y;
        c[0]=(int)c01.x; c[1]=(int)c01.y; c[2]=(int)c23.x; c[3]=(int)c23.y;
    }

    int2 o[4];
    #pragma unroll
    for (int j = 0; j < 4; ++j) {
        int rr = min(max(r[j], 0), N_NODES - 1);
        int cc = min(max(c[j], 0), N_NODES - 1);
        int pos = atomicAdd(&g_count[rr], 1);
        o[j] = make_int2((int)((unsigned)rr | ((unsigned)pos << 17)), cc);
    }
    int4* dst = reinterpret_cast<int4*>(g_p2) + 2*t;
    dst[0] = make_int4(o[0].x, o[0].y, o[1].x, o[1].y);
    dst[1] = make_int4(o[2].x, o[2].y, o[3].x, o[3].y);
}

// Segment assignment: warp-shuffle block scan + one atomicAdd per block to
// claim a contiguous base (segment order across blocks is arbitrary).
__global__ void __launch_bounds__(SCAN_BLK) assign_kernel() {
    __shared__ int warpsum[SCAN_BLK / 32];
    __shared__ int sbase;
    int t = threadIdx.x, lane = t & 31, wid = t >> 5;
    int i = blockIdx.x * SCAN_BLK + t;
    int v = (i < N_NODES) ? g_count[i] : 0;

    int inc = v;                                   // inclusive warp scan
    #pragma unroll
    for (int off = 1; off < 32; off <<= 1) {
        int a = __shfl_up_sync(0xFFFFFFFFu, inc, off);
        if (lane >= off) inc += a;
    }
    if (lane == 31) warpsum[wid] = inc;
    __syncthreads();
    if (wid == 0) {                                // scan the 16 warp sums
        int ws = (lane < SCAN_BLK / 32) ? warpsum[lane] : 0;
        int wi = ws;
        #pragma unroll
        for (int off = 1; off < 32; off <<= 1) {
            int a = __shfl_up_sync(0xFFFFFFFFu, wi, off);
            if (lane >= off) wi += a;
        }
        if (lane < SCAN_BLK / 32) warpsum[lane] = wi - ws;   // exclusive
        if (lane == (SCAN_BLK / 32) - 1) sbase = atomicAdd(&g_ctr, wi);
    }
    __syncthreads();
    if (i < N_NODES)
        g_seg[i] = make_int2(sbase + warpsum[wid] + inc - v, v);
}

// Atomic-free scatter, 4 edges/thread (MLP=4 on the random seg-gathers).
__global__ void __launch_bounds__(256) scatter_kernel(const float* __restrict__ w) {
    int t  = blockIdx.x * 256 + threadIdx.x;
    int e0 = t * 4;
    if (e0 >= N_EDGES) return;

    const int4* src = reinterpret_cast<const int4*>(g_p2) + 2*t;
    int4 a = __ldg(src);
    int4 b = __ldg(src + 1);
    float4 wv = __ldg(reinterpret_cast<const float4*>(w) + t);

    unsigned rp0 = (unsigned)a.x, rp1 = (unsigned)a.z;
    unsigned rp2 = (unsigned)b.x, rp3 = (unsigned)b.z;

    // 4 independent random loads (L2-resident 800KB table) -> overlapped
    int s0 = g_seg[rp0 & ROW_MASK].x;
    int s1 = g_seg[rp1 & ROW_MASK].x;
    int s2 = g_seg[rp2 & ROW_MASK].x;
    int s3 = g_seg[rp3 & ROW_MASK].x;

    g_cw[s0 + (rp0 >> 17)] = make_int2(a.y, __float_as_int(wv.x));
    g_cw[s1 + (rp1 >> 17)] = make_int2(a.w, __float_as_int(wv.y));
    g_cw[s2 + (rp2 >> 17)] = make_int2(b.y, __float_as_int(wv.z));
    g_cw[s3 + (rp3 >> 17)] = make_int2(b.w, __float_as_int(wv.w));
}

// ---------------------------------------------------------------------------
__device__ __forceinline__ void load_coefs(const float* __restrict__ gam, float c[4]) {
    c[0] = tanhf(gam[0]) * SCALING;
    c[1] = c[0] * tanhf(gam[1]) * SCALING;
    c[2] = c[1] * tanhf(gam[2]) * SCALING;
    c[3] = c[2] * tanhf(gam[3]) * SCALING;
}

// Fused SpMM (gather, atomic-free) + Jacobi recurrence + output accumulation.
// 16 threads per destination row; each thread owns one float4 of the 256B
// feature row. Per edge: one 8B broadcast load ({col,w}) + one 16B gather.
template <int LVL>
__global__ void __launch_bounds__(256) spmm_fused_kernel(
    const float* __restrict__ z,     // z_{l-1}
    const float* __restrict__ x,
    const float* __restrict__ gam,
    float* __restrict__ out)
{
    unsigned t    = blockIdx.x * 256u + threadIdx.x;
    unsigned row  = t >> 4;
    unsigned lane = t & 15u;

    int2 seg = __ldg(&g_seg[row]);
    int s = seg.x, e = seg.x + seg.y;
    const float4* zv = reinterpret_cast<const float4*>(z);

    float4 acc = make_float4(0.f, 0.f, 0.f, 0.f);
    #pragma unroll 4
    for (int k = s; k < e; ++k) {
        int2  cw = __ldg(&g_cw[k]);
        float wt = __int_as_float(cw.y);
        float4 v = __ldg(zv + (unsigned)cw.x * 16u + lane);
        acc.x += wt * v.x; acc.y += wt * v.y;
        acc.z += wt * v.z; acc.w += wt * v.w;
    }

    float c[4]; load_coefs(gam, c);
    unsigned i = row * 16u + lane;

    if (LVL == 1) {
        float4 z1 = make_float4(K1S * acc.x, K1S * acc.y, K1S * acc.z, K1S * acc.w);
        reinterpret_cast<float4*>(g_D1)[i] = z1;
        float4 xv = __ldg(reinterpret_cast<const float4*>(x) + i);
        float4 o;
        o.x = 0.25f * (c[0] * xv.x + c[1] * z1.x);
        o.y = 0.25f * (c[0] * xv.y + c[1] * z1.y);
        o.z = 0.25f * (c[0] * xv.z + c[1] * z1.z);
        o.w = 0.25f * (c[0] * xv.w + c[1] * z1.w);
        reinterpret_cast<float4*>(out)[i] = o;
    } else if (LVL == 2) {
        float4 xv = __ldg(reinterpret_cast<const float4*>(x) + i);
        float4 z2;
        z2.x = A2 * acc.x + B2 * xv.x;
        z2.y = A2 * acc.y + B2 * xv.y;
        z2.z = A2 * acc.z + B2 * xv.z;
        z2.w = A2 * acc.w + B2 * xv.w;
        reinterpret_cast<float4*>(g_D2)[i] = z2;
        float4 o = reinterpret_cast<float4*>(out)[i];
        float sc = 0.25f * c[2];
        o.x += sc * z2.x; o.y += sc * z2.y; o.z += sc * z2.z; o.w += sc * z2.w;
        reinterpret_cast<float4*>(out)[i] = o;
    } else {
        float4 d1 = reinterpret_cast<float4*>(g_D1)[i];
        float4 z3;
        z3.x = A3 * acc.x + B3 * d1.x;
        z3.y = A3 * acc.y + B3 * d1.y;
        z3.z = A3 * acc.z + B3 * d1.z;
        z3.w = A3 * acc.w + B3 * d1.w;
        float4 o = reinterpret_cast<float4*>(out)[i];
        float sc = 0.25f * c[3];
        o.x += sc * z3.x; o.y += sc * z3.y; o.z += sc * z3.z; o.w += sc * z3.w;
        reinterpret_cast<float4*>(out)[i] = o;
    }
}

// ---------------------------------------------------------------------------
extern "C" void kernel_launch(void* const* d_in, const int* in_sizes, int n_in,
                              void* d_out, int out_size)
{
    const float* x   = (const float*)d_in[0];
    const void*  ei  = d_in[1];
    const float* w   = (const float*)d_in[2];
    const float* gam = (const float*)d_in[3];
    float*       out = (float*)d_out;

    float* dD1;
    float* dD2;
    cudaGetSymbolAddress((void**)&dD1, g_D1);
    cudaGetSymbolAddress((void**)&dD2, g_D2);

    const int NB  = (N_NODES + 255) / 256;            // 391
    const int EB4 = (N_EDGES / 4 + 255) / 256;        // 1221
    const int RB  = (N_NODES * 16) / 256;             // 6250 (exact)

    // CSR build: 4 launches
    init_detect_kernel<<<NB, 256>>>((const unsigned*)ei);
    convert_hist_kernel<<<EB4, 256>>>(ei);
    assign_kernel<<<SCAN_NBLK, SCAN_BLK>>>();
    scatter_kernel<<<EB4, 256>>>(w);

    // Fused SpMM + recurrence + output accumulation: 3 launches
    spmm_fused_kernel<1><<<RB, 256>>>(x,   x, gam, out);
    spmm_fused_kernel<2><<<RB, 256>>>(dD1, x, gam, out);
    spmm_fused_kernel<3><<<RB, 256>>>(dD2, x, gam, out);
}

// round 11
// speedup vs baseline: 2.3788x; 1.0096x over previous
#include <cuda_runtime.h>

// JacobiConv: L=3, alpha=beta=1, SCALING=3 — CSR-gather, MLP-optimized build
// Inputs (metadata order):
//   d_in[0] x           : float32 [100000, 64]
//   d_in[1] edge_index  : int64 OR int32 [2, 1250000] (row=[0], col=[1]) — dtype detected at runtime
//   d_in[2] edge_weight : float32 [1250000]
//   d_in[3] gammas      : float32 [4, 1]
// Output: float32 [100000, 64]

static constexpr int N_NODES = 100000;
static constexpr int N_EDGES = 1250000;            // divisible by 4
static constexpr int NELEM   = N_NODES * 64;
static constexpr float SCALING = 3.0f;

// Recurrence constants (alpha = beta = 1):
static constexpr float K1S = 2.0f;              // z1 = 2*Az0
static constexpr float A2  = 120.0f / 64.0f;    // z2 = 1.875*Az1 - 0.75*z0
static constexpr float B2  = -48.0f / 64.0f;
static constexpr float A3  = 336.0f / 180.0f;   // z3 = 1.8667*Az2 - 0.8*z1
static constexpr float B3  = -144.0f / 180.0f;

static constexpr int SCAN_BLK  = 512;
static constexpr int SCAN_NBLK = (N_NODES + SCAN_BLK - 1) / SCAN_BLK;  // 196

// row in bits [0:17), pos-in-row in bits [17:32)
static constexpr unsigned ROW_MASK = 0x1FFFFu;

// Scratch (__device__ globals: allocation-free rule).
__device__ __align__(256) float g_D1[NELEM];       // z1
__device__ __align__(256) float g_D2[NELEM];       // z2
__device__ __align__(16)  int2  g_p2[N_EDGES];     // {row|pos<<17, col}
__device__ __align__(16)  int2  g_cw[N_EDGES];     // {col, w_bits} row-grouped
__device__ __align__(16)  int2  g_seg[N_NODES];    // {start, count}
__device__ int g_count[N_NODES];
__device__ int g_ctr;
__device__ unsigned g_i32flag;                     // 0 => int64 indices, 1 => int32

// ---------------------------------------------------------------------------
// Zero counters + detect edge_index dtype (block 0 samples 512 odd 32-bit
// words: int64 values <2^31 have zero high-halves; int32 data has random node
// ids there -> OR != 0 with certainty).
__global__ void __launch_bounds__(256) init_detect_kernel(const unsigned* __restrict__ ei32) {
    int i = blockIdx.x * 256 + threadIdx.x;
    if (i < N_NODES) g_count[i] = 0;
    if (blockIdx.x == 0) {
        if (threadIdx.x == 0) { g_ctr = 0; g_i32flag = 0u; }
        __syncthreads();
        unsigned v = ei32[2 * threadIdx.x + 1];
        v = __reduce_or_sync(0xFFFFFFFFu, v);
        if ((threadIdx.x & 31) == 0 && v) atomicOr(&g_i32flag, 1u);
    }
}

// Decode 4 edges/thread (vector loads), histogram rows; the atomic's return
// value IS the edge's position within its row, packed with the row id.
__global__ void __launch_bounds__(256) convert_hist_kernel(const void* __restrict__ ei) {
    int t  = blockIdx.x * 256 + threadIdx.x;
    int e0 = t * 4;
    if (e0 >= N_EDGES) return;

    int r[4], c[4];
    if (g_i32flag) {
        int4 rv = __ldg(reinterpret_cast<const int4*>(ei) + t);
        int4 cv = __ldg(reinterpret_cast<const int4*>((const int*)ei + N_EDGES) + t);
        r[0]=rv.x; r[1]=rv.y; r[2]=rv.z; r[3]=rv.w;
        c[0]=cv.x; c[1]=cv.y; c[2]=cv.z; c[3]=cv.w;
    } else {
        const longlong2* rp = reinterpret_cast<const longlong2*>(ei);
        const longlong2* cp = reinterpret_cast<const longlong2*>((const long long*)ei + N_EDGES);
        longlong2 r01 = __ldg(rp + 2*t), r23 = __ldg(rp + 2*t + 1);
        longlong2 c01 = __ldg(cp + 2*t), c23 = __ldg(cp + 2*t + 1);
        r[0]=(int)r01.x; r[1]=(int)r01.y; r[2]=(int)r23.x; r[3]=(int)r23.y;
        c[0]=(int)c01.x; c[1]=(int)c01.y; c[2]=(int)c23.x; c[3]=(int)c23.y;
    }

    int2 o[4];
    #pragma unroll
    for (int j = 0; j < 4; ++j) {
        int rr = min(max(r[j], 0), N_NODES - 1);
        int cc = min(max(c[j], 0), N_NODES - 1);
        int pos = atomicAdd(&g_count[rr], 1);
        o[j] = make_int2((int)((unsigned)rr | ((unsigned)pos << 17)), cc);
    }
    int4* dst = reinterpret_cast<int4*>(g_p2) + 2*t;
    dst[0] = make_int4(o[0].x, o[0].y, o[1].x, o[1].y);
    dst[1] = make_int4(o[2].x, o[2].y, o[3].x, o[3].y);
}

// Segment assignment: warp-shuffle block scan + one atomicAdd per block to
// claim a contiguous base (segment order across blocks is arbitrary).
__global__ void __launch_bounds__(SCAN_BLK) assign_kernel() {
    __shared__ int warpsum[SCAN_BLK / 32];
    __shared__ int sbase;
    int t = threadIdx.x, lane = t & 31, wid = t >> 5;
    int i = blockIdx.x * SCAN_BLK + t;
    int v = (i < N_NODES) ? g_count[i] : 0;

    int inc = v;                                   // inclusive warp scan
    #pragma unroll
    for (int off = 1; off < 32; off <<= 1) {
        int a = __shfl_up_sync(0xFFFFFFFFu, inc, off);
        if (lane >= off) inc += a;
    }
    if (lane == 31) warpsum[wid] = inc;
    __syncthreads();
    if (wid == 0) {                                // scan the 16 warp sums
        int ws = (lane < SCAN_BLK / 32) ? warpsum[lane] : 0;
        int wi = ws;
        #pragma unroll
        for (int off = 1; off < 32; off <<= 1) {
            int a = __shfl_up_sync(0xFFFFFFFFu, wi, off);
            if (lane >= off) wi += a;
        }
        if (lane < SCAN_BLK / 32) warpsum[lane] = wi - ws;   // exclusive
        if (lane == (SCAN_BLK / 32) - 1) sbase = atomicAdd(&g_ctr, wi);
    }
    __syncthreads();
    if (i < N_NODES)
        g_seg[i] = make_int2(sbase + warpsum[wid] + inc - v, v);
}

// Atomic-free scatter, 4 edges/thread (MLP=4 on the random seg-gathers).
__global__ void __launch_bounds__(256) scatter_kernel(const float* __restrict__ w) {
    int t  = blockIdx.x * 256 + threadIdx.x;
    int e0 = t * 4;
    if (e0 >= N_EDGES) return;

    const int4* src = reinterpret_cast<const int4*>(g_p2) + 2*t;
    int4 a = __ldg(src);
    int4 b = __ldg(src + 1);
    float4 wv = __ldg(reinterpret_cast<const float4*>(w) + t);

    unsigned rp0 = (unsigned)a.x, rp1 = (unsigned)a.z;
    unsigned rp2 = (unsigned)b.x, rp3 = (unsigned)b.z;

    // 4 independent random loads (L2-resident 800KB table) -> overlapped
    int s0 = g_seg[rp0 & ROW_MASK].x;
    int s1 = g_seg[rp1 & ROW_MASK].x;
    int s2 = g_seg[rp2 & ROW_MASK].x;
    int s3 = g_seg[rp3 & ROW_MASK].x;

    g_cw[s0 + (rp0 >> 17)] = make_int2(a.y, __float_as_int(wv.x));
    g_cw[s1 + (rp1 >> 17)] = make_int2(a.w, __float_as_int(wv.y));
    g_cw[s2 + (rp2 >> 17)] = make_int2(b.y, __float_as_int(wv.z));
    g_cw[s3 + (rp3 >> 17)] = make_int2(b.w, __float_as_int(wv.w));
}

// ---------------------------------------------------------------------------
__device__ __forceinline__ void load_coefs(const float* __restrict__ gam, float c[4]) {
    c[0] = tanhf(gam[0]) * SCALING;
    c[1] = c[0] * tanhf(gam[1]) * SCALING;
    c[2] = c[1] * tanhf(gam[2]) * SCALING;
    c[3] = c[2] * tanhf(gam[3]) * SCALING;
}

// Fused SpMM (gather, atomic-free) + Jacobi recurrence + output accumulation.
// 16 threads per destination row; each thread owns one float4 of the 256B
// feature row. Per edge: one 8B broadcast load ({col,w}) + one 16B gather.
template <int LVL>
__global__ void __launch_bounds__(256) spmm_fused_kernel(
    const float* __restrict__ z,     // z_{l-1}
    const float* __restrict__ x,
    const float* __restrict__ gam,
    float* __restrict__ out)
{
    unsigned t    = blockIdx.x * 256u + threadIdx.x;
    unsigned row  = t >> 4;
    unsigned lane = t & 15u;

    int2 seg = __ldg(&g_seg[row]);
    int s = seg.x, e = seg.x + seg.y;
    const float4* zv = reinterpret_cast<const float4*>(z);

    float4 acc = make_float4(0.f, 0.f, 0.f, 0.f);
    #pragma unroll 4
    for (int k = s; k < e; ++k) {
        int2  cw = __ldg(&g_cw[k]);
        float wt = __int_as_float(cw.y);
        float4 v = __ldg(zv + (unsigned)cw.x * 16u + lane);
        acc.x += wt * v.x; acc.y += wt * v.y;
        acc.z += wt * v.z; acc.w += wt * v.w;
    }

    float c[4]; load_coefs(gam, c);
    unsigned i = row * 16u + lane;

    if (LVL == 1) {
        float4 z1 = make_float4(K1S * acc.x, K1S * acc.y, K1S * acc.z, K1S * acc.w);
        reinterpret_cast<float4*>(g_D1)[i] = z1;
        float4 xv = __ldg(reinterpret_cast<const float4*>(x) + i);
        float4 o;
        o.x = 0.25f * (c[0] * xv.x + c[1] * z1.x);
        o.y = 0.25f * (c[0] * xv.y + c[1] * z1.y);
        o.z = 0.25f * (c[0] * xv.z + c[1] * z1.z);
        o.w = 0.25f * (c[0] * xv.w + c[1] * z1.w);
        reinterpret_cast<float4*>(out)[i] = o;
    } else if (LVL == 2) {
        float4 xv = __ldg(reinterpret_cast<const float4*>(x) + i);
        float4 z2;
        z2.x = A2 * acc.x + B2 * xv.x;
        z2.y = A2 * acc.y + B2 * xv.y;
        z2.z = A2 * acc.z + B2 * xv.z;
        z2.w = A2 * acc.w + B2 * xv.w;
        reinterpret_cast<float4*>(g_D2)[i] = z2;
        float4 o = reinterpret_cast<float4*>(out)[i];
        float sc = 0.25f * c[2];
        o.x += sc * z2.x; o.y += sc * z2.y; o.z += sc * z2.z; o.w += sc * z2.w;
        reinterpret_cast<float4*>(out)[i] = o;
    } else {
        float4 d1 = reinterpret_cast<float4*>(g_D1)[i];
        float4 z3;
        z3.x = A3 * acc.x + B3 * d1.x;
        z3.y = A3 * acc.y + B3 * d1.y;
        z3.z = A3 * acc.z + B3 * d1.z;
        z3.w = A3 * acc.w + B3 * d1.w;
        float4 o = reinterpret_cast<float4*>(out)[i];
        float sc = 0.25f * c[3];
        o.x += sc * z3.x; o.y += sc * z3.y; o.z += sc * z3.z; o.w += sc * z3.w;
        reinterpret_cast<float4*>(out)[i] = o;
    }
}

// ---------------------------------------------------------------------------
extern "C" void kernel_launch(void* const* d_in, const int* in_sizes, int n_in,
                              void* d_out, int out_size)
{
    const float* x   = (const float*)d_in[0];
    const void*  ei  = d_in[1];
    const float* w   = (const float*)d_in[2];
    const float* gam = (const float*)d_in[3];
    float*       out = (float*)d_out;

    float* dD1;
    float* dD2;
    cudaGetSymbolAddress((void**)&dD1, g_D1);
    cudaGetSymbolAddress((void**)&dD2, g_D2);

    const int NB  = (N_NODES + 255) / 256;            // 391
    const int EB4 = (N_EDGES / 4 + 255) / 256;        // 1221
    const int RB  = (N_NODES * 16) / 256;             // 6250 (exact)

    // CSR build: 4 launches
    init_detect_kernel<<<NB, 256>>>((const unsigned*)ei);
    convert_hist_kernel<<<EB4, 256>>>(ei);
    assign_kernel<<<SCAN_NBLK, SCAN_BLK>>>();
    scatter_kernel<<<EB4, 256>>>(w);

    // Fused SpMM + recurrence + output accumulation: 3 launches
    spmm_fused_kernel<1><<<RB, 256>>>(x,   x, gam, out);
    spmm_fused_kernel<2><<<RB, 256>>>(dD1, x, gam, out);
    spmm_fused_kernel<3><<<RB, 256>>>(dD2, x, gam, out);
}